// round 6
// baseline (speedup 1.0000x reference)
#include <cuda_runtime.h>
#include <cstdint>

// Problem constants
#define BD 64
#define H1 128
#define H2 32
#define G 8
#define F 8
#define E 4
#define AH 8
#define NH 2
#define OUTD 2

#define TPB 256
#define EPB 256          // elements per block

// shared strides
#define XSS 260          // Xs row stride (floats), %4==0 -> 16B rows
#define HSS 132          // H1s row stride
#define XHSS 33          // XHs row stride (odd -> conflict-free scalar col reads)

// shared offsets (floats)
#define W1S_OFF   0                          // [64][128]   8192
#define W2S_OFF   (W1S_OFF + BD * H1)        // [128][32]   4096
#define XS_OFF    (W2S_OFF + H1 * H2)        // [64][260]   16640
#define H1S_OFF   (XS_OFF + BD * XSS)        // [128][132]  16896
#define XHS_OFF   (H1S_OFF + H1 * HSS)       // [256][33]   8448
#define SB1_OFF   (XHS_OFF + EPB * XHSS)
#define SB2_OFF   (SB1_OFF + H1)
#define SMEAN_OFF (SB2_OFF + H2)
#define SINV_OFF  (SMEAN_OFF + BD)
#define SENW_OFF  (SINV_OFF + BD)
#define SENB_OFF  (SENW_OFF + G * F * E)
#define SM_OFF    (SENB_OFF + G * E)
#define SU_OFF    (SM_OFF + NH * 16)
#define SV_OFF    (SU_OFF + NH * 4)
#define SC_OFF    (SV_OFF + NH * 4)
#define SDW_OFF   (SC_OFF + NH)
#define SDB_OFF   (SDW_OFF + (H2 + 2 * G * E) * OUTD)
#define SMEM_FLOATS (SDB_OFF + OUTD)
#define SMEM_BYTES  (SMEM_FLOATS * 4)

// x-column swizzle: breaks k,k+8m bank collisions on staging writes,
// preserves 8-float block contiguity for GEMM1 vector reads.
#define XSWZ(k) ((((k) >> 3) & 3) << 3)

// ---- packed f32x2 helpers ----
__device__ __forceinline__ unsigned long long pk2(float lo, float hi) {
    unsigned long long r;
    asm("mov.b64 %0, {%1, %2};" : "=l"(r) : "f"(lo), "f"(hi));
    return r;
}
__device__ __forceinline__ void upk2(unsigned long long a, float& lo, float& hi) {
    asm("mov.b64 {%0, %1}, %2;" : "=f"(lo), "=f"(hi) : "l"(a));
}
__device__ __forceinline__ void fma2(unsigned long long& d, unsigned long long a, unsigned long long b) {
    asm("fma.rn.f32x2 %0, %1, %2, %0;" : "+l"(d) : "l"(a), "l"(b));
}

extern "C" __global__ void __launch_bounds__(TPB)
ggat_kernel(const float* __restrict__ x,
            const float* __restrict__ norm_mean,
            const float* __restrict__ norm_std,
            const float* __restrict__ w1,
            const float* __restrict__ b1,
            const float* __restrict__ w2,
            const float* __restrict__ b2,
            const float* __restrict__ encw,
            const float* __restrict__ encb,
            const float* __restrict__ srcw,
            const float* __restrict__ srcb,
            const float* __restrict__ dstw,
            const float* __restrict__ dstb,
            const float* __restrict__ decw,
            const float* __restrict__ decb,
            float* __restrict__ out,
            int n)
{
    extern __shared__ float sm[];
    float* sw1   = sm + W1S_OFF;
    float* sw2   = sm + W2S_OFF;
    float* sxs   = sm + XS_OFF;
    float* sh1   = sm + H1S_OFF;
    float* sxh   = sm + XHS_OFF;
    float* sb1   = sm + SB1_OFF;
    float* sb2   = sm + SB2_OFF;
    float* smean = sm + SMEAN_OFF;
    float* sinv  = sm + SINV_OFF;
    float* senw  = sm + SENW_OFF;
    float* senb  = sm + SENB_OFF;
    float* sM    = sm + SM_OFF;
    float* su    = sm + SU_OFF;
    float* sv    = sm + SV_OFF;
    float* sc    = sm + SC_OFF;
    float* sdw   = sm + SDW_OFF;
    float* sdb   = sm + SDB_OFF;

    const int tid = threadIdx.x;
    const int eblk = blockIdx.x * EPB;

    // ---------------- stage weights & tables ----------------
    for (int idx = tid; idx < BD * H1; idx += TPB) sw1[idx] = w1[idx];
    for (int idx = tid; idx < H1 * H2; idx += TPB) sw2[idx] = w2[idx];
    if (tid < H1) sb1[tid] = b1[tid];
    if (tid < H2) sb2[tid] = b2[tid];
    if (tid < BD) {
        smean[tid] = norm_mean[tid];
        sinv[tid]  = 1.0f / (norm_std[tid] + 1e-8f);
    }
    for (int idx = tid; idx < G * F * E; idx += TPB) senw[idx] = encw[idx];
    if (tid < G * E) senb[tid] = encb[tid];
    if (tid < (H2 + 2 * G * E) * OUTD) sdw[tid] = decw[tid];
    if (tid < OUTD) sdb[tid] = decb[tid];

    // attention precompute: score[g][k] = h_g M h_k^T + u.h_g + v.h_k + c
    if (tid < NH) {
        const int hh = tid;
        const float invs = rsqrtf((float)AH);
        for (int e = 0; e < E; e++)
            for (int e2 = 0; e2 < E; e2++) {
                float m = 0.f;
                for (int a = 0; a < AH; a++)
                    m = fmaf(srcw[e * (NH * AH) + hh * AH + a],
                             dstw[e2 * (NH * AH) + hh * AH + a], m);
                sM[hh * 16 + e * 4 + e2] = m * invs;
            }
        for (int e = 0; e < E; e++) {
            float uu = 0.f, vv = 0.f;
            for (int a = 0; a < AH; a++) {
                uu = fmaf(srcw[e * (NH * AH) + hh * AH + a], dstb[hh * AH + a], uu);
                vv = fmaf(dstw[e * (NH * AH) + hh * AH + a], srcb[hh * AH + a], vv);
            }
            su[hh * 4 + e] = uu * invs;
            sv[hh * 4 + e] = vv * invs;
        }
        float cc = 0.f;
        for (int a = 0; a < AH; a++)
            cc = fmaf(srcb[hh * AH + a], dstb[hh * AH + a], cc);
        sc[hh] = cc * invs;
    }

    // ---------------- stage x transposed (k-major, swizzled) ----------------
    // idx: consecutive tid -> consecutive k of same element -> coalesced LDG.
    for (int idx = tid; idx < EPB * BD; idx += TPB) {
        int e = idx >> 6;
        int k = idx & 63;
        int ge = eblk + e;
        float v = (ge < n) ? x[(size_t)ge * BD + k] : 0.0f;
        sxs[k * XSS + (e ^ XSWZ(k))] = v;
    }
    __syncthreads();

    const int tx = tid & 15;   // GEMM1 elem group (8 elems)
    const int ty = tid >> 4;   // GEMM1 h1 group (8 cols)
    const int u2 = tid & 7;    // GEMM2 col group (4 cols)
    const int v2 = tid >> 3;   // GEMM2 local-elem group (4 elems)

    for (int h = 0; h < 2; h++) {
        const int elocal = h * 128 + tx * 8;  // this thread's 8 elems (block-local)

        // ---------- GEMM1: C[8e x 8h1] = X[8e x 64] * W1[64 x 8h1] ----------
        unsigned long long c2[8][4];
#pragma unroll
        for (int jj = 0; jj < 8; jj++) {
            float bb = sb1[ty * 8 + jj];
            unsigned long long bp = pk2(bb, bb);
#pragma unroll
            for (int p = 0; p < 4; p++) c2[jj][p] = bp;
        }

#pragma unroll 8
        for (int k = 0; k < BD; k++) {
            const float* ap = sxs + k * XSS + (elocal ^ XSWZ(k));
            float4 a0 = *reinterpret_cast<const float4*>(ap);
            float4 a1 = *reinterpret_cast<const float4*>(ap + 4);
            unsigned long long a2[4];
            a2[0] = pk2(a0.x, a0.y); a2[1] = pk2(a0.z, a0.w);
            a2[2] = pk2(a1.x, a1.y); a2[3] = pk2(a1.z, a1.w);
            const float* wp = sw1 + k * H1 + ty * 8;
            float4 b0 = *reinterpret_cast<const float4*>(wp);
            float4 b1 = *reinterpret_cast<const float4*>(wp + 4);
            float bv[8] = {b0.x, b0.y, b0.z, b0.w, b1.x, b1.y, b1.z, b1.w};
#pragma unroll
            for (int jj = 0; jj < 8; jj++) {
                unsigned long long bd = pk2(bv[jj], bv[jj]);
                fma2(c2[jj][0], a2[0], bd);
                fma2(c2[jj][1], a2[1], bd);
                fma2(c2[jj][2], a2[2], bd);
                fma2(c2[jj][3], a2[3], bd);
            }
        }

        // relu + store H1s[j][e_local]
#pragma unroll
        for (int jj = 0; jj < 8; jj++) {
            float r[8];
#pragma unroll
            for (int p = 0; p < 4; p++) {
                float lo, hi;
                upk2(c2[jj][p], lo, hi);
                r[2 * p]     = fmaxf(lo, 0.f);
                r[2 * p + 1] = fmaxf(hi, 0.f);
            }
            float* hp = sh1 + (ty * 8 + jj) * HSS + tx * 8;
            *reinterpret_cast<float4*>(hp)     = make_float4(r[0], r[1], r[2], r[3]);
            *reinterpret_cast<float4*>(hp + 4) = make_float4(r[4], r[5], r[6], r[7]);
        }
        __syncthreads();

        // ---------- GEMM2: C2[4e x 4c] = H1[4e x 128] * W2[128 x 4c] ----------
        unsigned long long d2[4][2];
        {
            unsigned long long s0 = pk2(sb2[u2 * 4],     sb2[u2 * 4 + 1]);
            unsigned long long s1 = pk2(sb2[u2 * 4 + 2], sb2[u2 * 4 + 3]);
#pragma unroll
            for (int ee = 0; ee < 4; ee++) { d2[ee][0] = s0; d2[ee][1] = s1; }
        }

#pragma unroll 8
        for (int k2 = 0; k2 < H1; k2++) {
            float4 av = *reinterpret_cast<const float4*>(sh1 + k2 * HSS + v2 * 4);
            float4 bw = *reinterpret_cast<const float4*>(sw2 + k2 * H2 + u2 * 4);
            unsigned long long bb0 = pk2(bw.x, bw.y);
            unsigned long long bb1 = pk2(bw.z, bw.w);
            float aa[4] = {av.x, av.y, av.z, av.w};
#pragma unroll
            for (int ee = 0; ee < 4; ee++) {
                unsigned long long ad = pk2(aa[ee], aa[ee]);
                fma2(d2[ee][0], ad, bb0);
                fma2(d2[ee][1], ad, bb1);
            }
        }

        // relu + store XHs[e][c] (scalar, conflict-free stride 33)
#pragma unroll
        for (int ee = 0; ee < 4; ee++) {
            int le = h * 128 + v2 * 4 + ee;
            float lo0, hi0, lo1, hi1;
            upk2(d2[ee][0], lo0, hi0);
            upk2(d2[ee][1], lo1, hi1);
            float* xp_ = sxh + le * XHSS + u2 * 4;
            xp_[0] = fmaxf(lo0, 0.f);
            xp_[1] = fmaxf(hi0, 0.f);
            xp_[2] = fmaxf(lo1, 0.f);
            xp_[3] = fmaxf(hi1, 0.f);
        }
        __syncthreads();
    }

    // ---------------- epilogue: one thread per element ----------------
    const int e = tid;
    const int ge = eblk + e;

    // encoder
    float hv[G * E];
#pragma unroll
    for (int g = 0; g < G; g++) {
        float xn[F];
#pragma unroll
        for (int f = 0; f < F; f++) {
            int k = g * 8 + f;
            float xv = sxs[k * XSS + (e ^ XSWZ(k))];
            xn[f] = (xv - smean[k]) * sinv[k];
        }
#pragma unroll
        for (int ee = 0; ee < E; ee++) {
            float acc = senb[g * E + ee];
#pragma unroll
            for (int f = 0; f < F; f++)
                acc = fmaf(xn[f], senw[g * (F * E) + f * E + ee], acc);
            hv[g * E + ee] = fmaxf(acc, 0.f);
        }
    }

    // attention
    float att[G * E];
#pragma unroll
    for (int i = 0; i < G * E; i++) att[i] = 0.f;

#pragma unroll
    for (int hh = 0; hh < NH; hh++) {
        float t[G * E];
        float sg[G], dk[G];
#pragma unroll
        for (int g = 0; g < G; g++) {
#pragma unroll
            for (int e2 = 0; e2 < E; e2++) {
                float acc = 0.f;
#pragma unroll
                for (int ee = 0; ee < E; ee++)
                    acc = fmaf(hv[g * E + ee], sM[hh * 16 + ee * 4 + e2], acc);
                t[g * E + e2] = acc;
            }
            float a1 = 0.f, a2_ = 0.f;
#pragma unroll
            for (int ee = 0; ee < E; ee++) {
                a1  = fmaf(hv[g * E + ee], su[hh * 4 + ee], a1);
                a2_ = fmaf(hv[g * E + ee], sv[hh * 4 + ee], a2_);
            }
            sg[g] = a1;
            dk[g] = a2_;
        }
        const float cc = sc[hh];
#pragma unroll
        for (int g = 0; g < G; g++) {
            float s[G];
            float mx = -1e30f;
#pragma unroll
            for (int k = 0; k < G; k++) {
                float acc = sg[g] + dk[k] + cc;
#pragma unroll
                for (int e2 = 0; e2 < E; e2++)
                    acc = fmaf(t[g * E + e2], hv[k * E + e2], acc);
                s[k] = acc;
                mx = fmaxf(mx, acc);
            }
            float p[G];
            float sum = 0.f;
#pragma unroll
            for (int k = 0; k < G; k++) {
                p[k] = __expf(s[k] - mx);
                sum += p[k];
            }
            float inv = 1.0f / sum;
#pragma unroll
            for (int k = 0; k < G; k++) {
                float pk = p[k] * inv;
#pragma unroll
                for (int ee = 0; ee < E; ee++)
                    att[g * E + ee] = fmaf(pk, hv[k * E + ee], att[g * E + ee]);
            }
        }
    }

    // decoder
    float o0 = sdb[0], o1 = sdb[1];
#pragma unroll
    for (int i = 0; i < H2; i++) {
        float xh = sxh[e * XHSS + i];
        o0 = fmaf(xh, sdw[i * 2 + 0], o0);
        o1 = fmaf(xh, sdw[i * 2 + 1], o1);
    }
#pragma unroll
    for (int i = 0; i < G * E; i++) {
        o0 = fmaf(hv[i], sdw[(H2 + i) * 2 + 0], o0);
        o1 = fmaf(hv[i], sdw[(H2 + i) * 2 + 1], o1);
    }
#pragma unroll
    for (int i = 0; i < G * E; i++) {
        o0 = fmaf(att[i], sdw[(H2 + G * E + i) * 2 + 0], o0);
        o1 = fmaf(att[i], sdw[(H2 + G * E + i) * 2 + 1], o1);
    }

    if (ge < n) {
        float2 r;
        r.x = o0;
        r.y = o1;
        reinterpret_cast<float2*>(out)[ge] = r;
    }
}

extern "C" void kernel_launch(void* const* d_in, const int* in_sizes, int n_in,
                              void* d_out, int out_size)
{
    const float* x     = (const float*)d_in[0];
    const float* mean_ = (const float*)d_in[1];
    const float* std_  = (const float*)d_in[2];
    const float* w1    = (const float*)d_in[3];
    const float* b1    = (const float*)d_in[4];
    const float* w2    = (const float*)d_in[5];
    const float* b2    = (const float*)d_in[6];
    const float* encw  = (const float*)d_in[7];
    const float* encb  = (const float*)d_in[8];
    const float* srcw  = (const float*)d_in[9];
    const float* srcb  = (const float*)d_in[10];
    const float* dstw  = (const float*)d_in[11];
    const float* dstb  = (const float*)d_in[12];
    const float* decw  = (const float*)d_in[13];
    const float* decb  = (const float*)d_in[14];
    float* out = (float*)d_out;

    int n = in_sizes[0] / BD;

    cudaFuncSetAttribute(ggat_kernel,
                         cudaFuncAttributeMaxDynamicSharedMemorySize, SMEM_BYTES);

    dim3 grid((n + EPB - 1) / EPB);
    ggat_kernel<<<grid, TPB, SMEM_BYTES>>>(x, mean_, std_, w1, b1, w2, b2,
                                           encw, encb, srcw, srcb, dstw, dstb,
                                           decw, decb, out, n);
}

// round 8
// speedup vs baseline: 1.1953x; 1.1953x over previous
#include <cuda_runtime.h>
#include <cstdint>

// Problem constants
#define BD 64
#define H1 128
#define H2 32
#define G 8
#define F 8
#define E 4
#define AH 8
#define NH 2
#define OUTD 2

#define NMAX 524288

// 64MB scratch for xh (relu'd H2 activations), written by mlp_kernel,
// read by epi_kernel. __device__ global array = sanctioned scratch.
__device__ float g_xh[(size_t)NMAX * H2];

// ---- packed f32x2 helpers ----
__device__ __forceinline__ unsigned long long pk2(float lo, float hi) {
    unsigned long long r;
    asm("mov.b64 %0, {%1, %2};" : "=l"(r) : "f"(lo), "f"(hi));
    return r;
}
__device__ __forceinline__ void upk2(unsigned long long a, float& lo, float& hi) {
    asm("mov.b64 {%0, %1}, %2;" : "=f"(lo), "=f"(hi) : "l"(a));
}
__device__ __forceinline__ void fma2(unsigned long long& d, unsigned long long a, unsigned long long b) {
    asm("fma.rn.f32x2 %0, %1, %2, %0;" : "+l"(d) : "l"(a), "l"(b));
}

// ================= kernel 1: MLP GEMM (64 -> 128 -> 32) =================
#define TPB1 256
#define EPB1 128
#define XSS1 132        // Xs row stride (floats): 64 rows x 128 elems (+pad)
#define HSS1 128        // H1s row stride (floats): 128 rows x 128 elems EXACT
                        // (132 would push smem past the 2-CTA/SM limit)

// smem layout (floats)
#define K1_W1 0                        // [64][128]  8192
#define K1_W2 (K1_W1 + BD * H1)        // [128][32]  4096
#define K1_B1 (K1_W2 + H1 * H2)        // 128
#define K1_B2 (K1_B1 + H1)             // 32
#define K1_UN (K1_B2 + H2)             // union: Xs[64][132]=8448 | H1s[128][128]=16384
#define K1_FLOATS (K1_UN + H1 * HSS1)  // 28832
#define K1_BYTES (K1_FLOATS * 4)       // 115328  (fits 2 CTAs/SM on sm_100a)

extern "C" __global__ void __launch_bounds__(TPB1, 2)
mlp_kernel(const float* __restrict__ x,
           const float* __restrict__ w1, const float* __restrict__ b1,
           const float* __restrict__ w2, const float* __restrict__ b2,
           int n)
{
    extern __shared__ float sm[];
    float* sw1 = sm + K1_W1;   // [k][j]
    float* sw2 = sm + K1_W2;   // [j][c]
    float* sb1 = sm + K1_B1;
    float* sb2 = sm + K1_B2;
    float* sxs = sm + K1_UN;   // Xs[k][e]  (phase 1)
    float* sh1 = sm + K1_UN;   // H1s[j][e] (phase 2, aliases Xs)

    const int tid = threadIdx.x;
    const int eblk = blockIdx.x * EPB1;

    for (int i = tid; i < BD * H1; i += TPB1) sw1[i] = w1[i];
    for (int i = tid; i < H1 * H2; i += TPB1) sw2[i] = w2[i];
    if (tid < H1) sb1[tid] = b1[tid];
    if (tid < H2) sb2[tid] = b2[tid];

    // stage x transposed: Xs[k][e]; consecutive tid = consecutive k (coalesced LDG)
    for (int i = tid; i < EPB1 * BD; i += TPB1) {
        int e = i >> 6;
        int k = i & 63;
        int ge = eblk + e;
        sxs[k * XSS1 + e] = (ge < n) ? x[(size_t)ge * BD + k] : 0.0f;
    }
    __syncthreads();

    // ---------- GEMM1: H1[128e x 128j] ----------
    // thread (tx,ty): elems {tx*4..tx*4+3} and {64+tx*4..}, j's {ty*8..ty*8+7}
    const int tx = tid & 15;
    const int ty = tid >> 4;

    unsigned long long c2[8][4];
#pragma unroll
    for (int jj = 0; jj < 8; jj++) {
        float bb = sb1[ty * 8 + jj];
        unsigned long long bp = pk2(bb, bb);
#pragma unroll
        for (int p = 0; p < 4; p++) c2[jj][p] = bp;
    }

#pragma unroll 2
    for (int k = 0; k < BD; k++) {
        const float* xr = sxs + k * XSS1;
        float4 a0 = *reinterpret_cast<const float4*>(xr + tx * 4);
        float4 a1 = *reinterpret_cast<const float4*>(xr + 64 + tx * 4);
        unsigned long long a2[4];
        a2[0] = pk2(a0.x, a0.y); a2[1] = pk2(a0.z, a0.w);
        a2[2] = pk2(a1.x, a1.y); a2[3] = pk2(a1.z, a1.w);
        const float* wr = sw1 + k * H1 + ty * 8;
        float4 b0 = *reinterpret_cast<const float4*>(wr);
        float4 b1 = *reinterpret_cast<const float4*>(wr + 4);
        float bv[8] = {b0.x, b0.y, b0.z, b0.w, b1.x, b1.y, b1.z, b1.w};
#pragma unroll
        for (int jj = 0; jj < 8; jj++) {
            unsigned long long bd = pk2(bv[jj], bv[jj]);
            fma2(c2[jj][0], a2[0], bd);
            fma2(c2[jj][1], a2[1], bd);
            fma2(c2[jj][2], a2[2], bd);
            fma2(c2[jj][3], a2[3], bd);
        }
    }
    __syncthreads();   // all Xs reads done; safe to overwrite with H1s

    // relu + store H1s[j][e]   (rows are exactly 128 floats wide)
#pragma unroll
    for (int jj = 0; jj < 8; jj++) {
        float r[8];
#pragma unroll
        for (int p = 0; p < 4; p++) {
            float lo, hi;
            upk2(c2[jj][p], lo, hi);
            r[2 * p]     = fmaxf(lo, 0.f);
            r[2 * p + 1] = fmaxf(hi, 0.f);
        }
        float* hp = sh1 + (ty * 8 + jj) * HSS1;
        *reinterpret_cast<float4*>(hp + tx * 4)      = make_float4(r[0], r[1], r[2], r[3]);
        *reinterpret_cast<float4*>(hp + 64 + tx * 4) = make_float4(r[4], r[5], r[6], r[7]);
    }
    __syncthreads();

    // ---------- GEMM2: XH[128e x 32c] ----------
    // thread (v2,u2): elems v2*4..+3, cols u2*4..+3
    const int u2 = tid & 7;
    const int v2 = tid >> 3;

    unsigned long long d2[4][2];
    {
        unsigned long long s0 = pk2(sb2[u2 * 4],     sb2[u2 * 4 + 1]);
        unsigned long long s1 = pk2(sb2[u2 * 4 + 2], sb2[u2 * 4 + 3]);
#pragma unroll
        for (int ee = 0; ee < 4; ee++) { d2[ee][0] = s0; d2[ee][1] = s1; }
    }

#pragma unroll 4
    for (int k2 = 0; k2 < H1; k2++) {
        float4 av = *reinterpret_cast<const float4*>(sh1 + k2 * HSS1 + v2 * 4);
        float4 bw = *reinterpret_cast<const float4*>(sw2 + k2 * H2 + u2 * 4);
        unsigned long long bb0 = pk2(bw.x, bw.y);
        unsigned long long bb1 = pk2(bw.z, bw.w);
        float aa[4] = {av.x, av.y, av.z, av.w};
#pragma unroll
        for (int ee = 0; ee < 4; ee++) {
            unsigned long long ad = pk2(aa[ee], aa[ee]);
            fma2(d2[ee][0], ad, bb0);
            fma2(d2[ee][1], ad, bb1);
        }
    }

    // relu + store xh to global scratch
#pragma unroll
    for (int ee = 0; ee < 4; ee++) {
        int ge = eblk + v2 * 4 + ee;
        if (ge < n) {
            float lo0, hi0, lo1, hi1;
            upk2(d2[ee][0], lo0, hi0);
            upk2(d2[ee][1], lo1, hi1);
            float4 r = make_float4(fmaxf(lo0, 0.f), fmaxf(hi0, 0.f),
                                   fmaxf(lo1, 0.f), fmaxf(hi1, 0.f));
            *reinterpret_cast<float4*>(g_xh + (size_t)ge * H2 + u2 * 4) = r;
        }
    }
}

// ================= kernel 2: encoder + attention + decoder =================
#define TPB2 128

// smem (floats)
#define K2_MEAN 0
#define K2_INV  (K2_MEAN + BD)
#define K2_ENW  (K2_INV + BD)
#define K2_ENB  (K2_ENW + G * F * E)
#define K2_M    (K2_ENB + G * E)
#define K2_U    (K2_M + NH * 16)
#define K2_V    (K2_U + NH * 4)
#define K2_C    (K2_V + NH * 4)
#define K2_DW   (K2_C + NH)
#define K2_DB   (K2_DW + (H2 + 2 * G * E) * OUTD)
#define K2_FLOATS (K2_DB + OUTD)

extern "C" __global__ void __launch_bounds__(TPB2)
epi_kernel(const float* __restrict__ x,
           const float* __restrict__ norm_mean,
           const float* __restrict__ norm_std,
           const float* __restrict__ encw, const float* __restrict__ encb,
           const float* __restrict__ srcw, const float* __restrict__ srcb,
           const float* __restrict__ dstw, const float* __restrict__ dstb,
           const float* __restrict__ decw, const float* __restrict__ decb,
           float* __restrict__ out, int n)
{
    __shared__ float sm[K2_FLOATS];
    float* smean = sm + K2_MEAN;
    float* sinv  = sm + K2_INV;
    float* senw  = sm + K2_ENW;
    float* senb  = sm + K2_ENB;
    float* sM    = sm + K2_M;
    float* su    = sm + K2_U;
    float* sv    = sm + K2_V;
    float* sc    = sm + K2_C;
    float* sdw   = sm + K2_DW;
    float* sdb   = sm + K2_DB;

    const int tid = threadIdx.x;

    if (tid < BD) {
        smean[tid] = norm_mean[tid];
        sinv[tid]  = 1.0f / (norm_std[tid] + 1e-8f);
    }
    for (int i = tid; i < G * F * E; i += TPB2) senw[i] = encw[i];
    if (tid < G * E) senb[tid] = encb[tid];
    for (int i = tid; i < (H2 + 2 * G * E) * OUTD; i += TPB2) sdw[i] = decw[i];
    if (tid < OUTD) sdb[tid] = decb[tid];

    if (tid < NH) {
        const int hh = tid;
        const float invs = rsqrtf((float)AH);
        for (int e = 0; e < E; e++)
            for (int e2 = 0; e2 < E; e2++) {
                float m = 0.f;
                for (int a = 0; a < AH; a++)
                    m = fmaf(srcw[e * (NH * AH) + hh * AH + a],
                             dstw[e2 * (NH * AH) + hh * AH + a], m);
                sM[hh * 16 + e * 4 + e2] = m * invs;
            }
        for (int e = 0; e < E; e++) {
            float uu = 0.f, vv = 0.f;
            for (int a = 0; a < AH; a++) {
                uu = fmaf(srcw[e * (NH * AH) + hh * AH + a], dstb[hh * AH + a], uu);
                vv = fmaf(dstw[e * (NH * AH) + hh * AH + a], srcb[hh * AH + a], vv);
            }
            su[hh * 4 + e] = uu * invs;
            sv[hh * 4 + e] = vv * invs;
        }
        float cc = 0.f;
        for (int a = 0; a < AH; a++)
            cc = fmaf(srcb[hh * AH + a], dstb[hh * AH + a], cc);
        sc[hh] = cc * invs;
    }
    __syncthreads();

    const int e = blockIdx.x * TPB2 + tid;
    if (e >= n) return;

    // encoder (x streamed from gmem per group)
    float hv[G * E];
    const float4* xr = reinterpret_cast<const float4*>(x + (size_t)e * BD);
#pragma unroll
    for (int g = 0; g < G; g++) {
        float4 va = __ldg(xr + g * 2);
        float4 vb = __ldg(xr + g * 2 + 1);
        float xn[F];
        int d = g * 8;
        xn[0] = (va.x - smean[d])     * sinv[d];
        xn[1] = (va.y - smean[d + 1]) * sinv[d + 1];
        xn[2] = (va.z - smean[d + 2]) * sinv[d + 2];
        xn[3] = (va.w - smean[d + 3]) * sinv[d + 3];
        xn[4] = (vb.x - smean[d + 4]) * sinv[d + 4];
        xn[5] = (vb.y - smean[d + 5]) * sinv[d + 5];
        xn[6] = (vb.z - smean[d + 6]) * sinv[d + 6];
        xn[7] = (vb.w - smean[d + 7]) * sinv[d + 7];
#pragma unroll
        for (int ee = 0; ee < E; ee++) {
            float acc = senb[g * E + ee];
#pragma unroll
            for (int f = 0; f < F; f++)
                acc = fmaf(xn[f], senw[g * (F * E) + f * E + ee], acc);
            hv[g * E + ee] = fmaxf(acc, 0.f);
        }
    }

    // attention
    float att[G * E];
#pragma unroll
    for (int i = 0; i < G * E; i++) att[i] = 0.f;

#pragma unroll
    for (int hh = 0; hh < NH; hh++) {
        float t[G * E];
        float sg[G], dk[G];
#pragma unroll
        for (int g = 0; g < G; g++) {
#pragma unroll
            for (int e2 = 0; e2 < E; e2++) {
                float acc = 0.f;
#pragma unroll
                for (int ee = 0; ee < E; ee++)
                    acc = fmaf(hv[g * E + ee], sM[hh * 16 + ee * 4 + e2], acc);
                t[g * E + e2] = acc;
            }
            float a1 = 0.f, a2_ = 0.f;
#pragma unroll
            for (int ee = 0; ee < E; ee++) {
                a1  = fmaf(hv[g * E + ee], su[hh * 4 + ee], a1);
                a2_ = fmaf(hv[g * E + ee], sv[hh * 4 + ee], a2_);
            }
            sg[g] = a1;
            dk[g] = a2_;
        }
        const float cc = sc[hh];
#pragma unroll
        for (int g = 0; g < G; g++) {
            float s[G];
            float mx = -1e30f;
#pragma unroll
            for (int k = 0; k < G; k++) {
                float acc = sg[g] + dk[k] + cc;
#pragma unroll
                for (int e2 = 0; e2 < E; e2++)
                    acc = fmaf(t[g * E + e2], hv[k * E + e2], acc);
                s[k] = acc;
                mx = fmaxf(mx, acc);
            }
            float p[G];
            float sum = 0.f;
#pragma unroll
            for (int k = 0; k < G; k++) {
                p[k] = __expf(s[k] - mx);
                sum += p[k];
            }
            float inv = 1.0f / sum;
#pragma unroll
            for (int k = 0; k < G; k++) {
                float pk = p[k] * inv;
#pragma unroll
                for (int ee = 0; ee < E; ee++)
                    att[g * E + ee] = fmaf(pk, hv[k * E + ee], att[g * E + ee]);
            }
        }
    }

    // decoder: xh streamed from scratch
    float o0 = sdb[0], o1 = sdb[1];
    const float4* xhr = reinterpret_cast<const float4*>(g_xh + (size_t)e * H2);
#pragma unroll
    for (int q = 0; q < 8; q++) {
        float4 v = __ldg(xhr + q);
        int i = q * 4;
        o0 = fmaf(v.x, sdw[i * 2 + 0], o0);      o1 = fmaf(v.x, sdw[i * 2 + 1], o1);
        o0 = fmaf(v.y, sdw[(i + 1) * 2 + 0], o0); o1 = fmaf(v.y, sdw[(i + 1) * 2 + 1], o1);
        o0 = fmaf(v.z, sdw[(i + 2) * 2 + 0], o0); o1 = fmaf(v.z, sdw[(i + 2) * 2 + 1], o1);
        o0 = fmaf(v.w, sdw[(i + 3) * 2 + 0], o0); o1 = fmaf(v.w, sdw[(i + 3) * 2 + 1], o1);
    }
#pragma unroll
    for (int i = 0; i < G * E; i++) {
        o0 = fmaf(hv[i], sdw[(H2 + i) * 2 + 0], o0);
        o1 = fmaf(hv[i], sdw[(H2 + i) * 2 + 1], o1);
    }
#pragma unroll
    for (int i = 0; i < G * E; i++) {
        o0 = fmaf(att[i], sdw[(H2 + G * E + i) * 2 + 0], o0);
        o1 = fmaf(att[i], sdw[(H2 + G * E + i) * 2 + 1], o1);
    }

    float2 r;
    r.x = o0;
    r.y = o1;
    reinterpret_cast<float2*>(out)[e] = r;
}

extern "C" void kernel_launch(void* const* d_in, const int* in_sizes, int n_in,
                              void* d_out, int out_size)
{
    const float* x     = (const float*)d_in[0];
    const float* mean_ = (const float*)d_in[1];
    const float* std_  = (const float*)d_in[2];
    const float* w1    = (const float*)d_in[3];
    const float* b1    = (const float*)d_in[4];
    const float* w2    = (const float*)d_in[5];
    const float* b2    = (const float*)d_in[6];
    const float* encw  = (const float*)d_in[7];
    const float* encb  = (const float*)d_in[8];
    const float* srcw  = (const float*)d_in[9];
    const float* srcb  = (const float*)d_in[10];
    const float* dstw  = (const float*)d_in[11];
    const float* dstb  = (const float*)d_in[12];
    const float* decw  = (const float*)d_in[13];
    const float* decb  = (const float*)d_in[14];
    float* out = (float*)d_out;

    int n = in_sizes[0] / BD;

    cudaFuncSetAttribute(mlp_kernel,
                         cudaFuncAttributeMaxDynamicSharedMemorySize, K1_BYTES);

    dim3 g1((n + EPB1 - 1) / EPB1);
    mlp_kernel<<<g1, TPB1, K1_BYTES>>>(x, w1, b1, w2, b2, n);

    dim3 g2((n + TPB2 - 1) / TPB2);
    epi_kernel<<<g2, TPB2>>>(x, mean_, std_, encw, encb,
                             srcw, srcb, dstw, dstb, decw, decb, out, n);
}

// round 9
// speedup vs baseline: 1.2631x; 1.0567x over previous
#include <cuda_runtime.h>
#include <cstdint>

// Problem constants
#define BD 64
#define H1 128
#define H2 32
#define G 8
#define F 8
#define E 4
#define AH 8
#define NH 2
#define OUTD 2

#define NMAX 524288

// 4MB scratch: per-element float2 partial (xh @ dec_w rows 0..31),
// written by mlp_kernel tail, added by epi_kernel.
__device__ float2 g_part[NMAX];

// ---- packed f32x2 helpers ----
__device__ __forceinline__ unsigned long long pk2(float lo, float hi) {
    unsigned long long r;
    asm("mov.b64 %0, {%1, %2};" : "=l"(r) : "f"(lo), "f"(hi));
    return r;
}
__device__ __forceinline__ void upk2(unsigned long long a, float& lo, float& hi) {
    asm("mov.b64 {%0, %1}, %2;" : "=f"(lo), "=f"(hi) : "l"(a));
}
__device__ __forceinline__ void fma2(unsigned long long& d, unsigned long long a, unsigned long long b) {
    asm("fma.rn.f32x2 %0, %1, %2, %0;" : "+l"(d) : "l"(a), "l"(b));
}

// ================= kernel 1: MLP GEMM (64 -> 128 -> 32) + dec partial =====
#define TPB1 256
#define EPB1 128
#define XSS1 132        // Xs row stride (floats)
#define HSS1 128        // H1s row stride (floats), exact width

// smem layout (floats)
#define K1_W1  0                        // [64][128]  8192
#define K1_W2  (K1_W1 + BD * H1)        // [128][32]  4096
#define K1_B1  (K1_W2 + H1 * H2)        // 128
#define K1_B2  (K1_B1 + H1)             // 32
#define K1_DW2 (K1_B2 + H2)             // 64 (dec_w rows 0..31, 2 outs)
#define K1_UN  (K1_DW2 + 2 * H2)        // union: Xs[64][132]=8448 | H1s[128][128]=16384
#define K1_FLOATS (K1_UN + H1 * HSS1)   // 28896
#define K1_BYTES (K1_FLOATS * 4)        // 115584 (2 CTAs/SM)

extern "C" __global__ void __launch_bounds__(TPB1, 2)
mlp_kernel(const float* __restrict__ x,
           const float* __restrict__ w1, const float* __restrict__ b1,
           const float* __restrict__ w2, const float* __restrict__ b2,
           const float* __restrict__ decw,
           int n)
{
    extern __shared__ float sm[];
    float* sw1  = sm + K1_W1;   // [k][j]
    float* sw2  = sm + K1_W2;   // [j][c]
    float* sb1  = sm + K1_B1;
    float* sb2  = sm + K1_B2;
    float* sdw2 = sm + K1_DW2;  // decw[0..63]
    float* sxs  = sm + K1_UN;   // Xs[k][e]  (phase 1)
    float* sh1  = sm + K1_UN;   // H1s[j][e] (phase 2, aliases Xs)

    const int tid = threadIdx.x;
    const int eblk = blockIdx.x * EPB1;

    // vectorized weight staging
    {
        const float4* w1v = reinterpret_cast<const float4*>(w1);
        float4* s1v = reinterpret_cast<float4*>(sw1);
        for (int i = tid; i < BD * H1 / 4; i += TPB1) s1v[i] = w1v[i];
        const float4* w2v = reinterpret_cast<const float4*>(w2);
        float4* s2v = reinterpret_cast<float4*>(sw2);
        for (int i = tid; i < H1 * H2 / 4; i += TPB1) s2v[i] = w2v[i];
    }
    if (tid < H1) sb1[tid] = b1[tid];
    if (tid < H2) sb2[tid] = b2[tid];
    if (tid < 2 * H2) sdw2[tid] = decw[tid];

    // stage x transposed: Xs[k][e]
    for (int i = tid; i < EPB1 * BD; i += TPB1) {
        int e = i >> 6;
        int k = i & 63;
        int ge = eblk + e;
        sxs[k * XSS1 + e] = (ge < n) ? x[(size_t)ge * BD + k] : 0.0f;
    }
    __syncthreads();

    // ---------- GEMM1: H1[128e x 128j] ----------
    const int tx = tid & 15;
    const int ty = tid >> 4;

    unsigned long long c2[8][4];
#pragma unroll
    for (int jj = 0; jj < 8; jj++) {
        float bb = sb1[ty * 8 + jj];
        unsigned long long bp = pk2(bb, bb);
#pragma unroll
        for (int p = 0; p < 4; p++) c2[jj][p] = bp;
    }

#pragma unroll 2
    for (int k = 0; k < BD; k++) {
        const float* xr = sxs + k * XSS1;
        float4 a0 = *reinterpret_cast<const float4*>(xr + tx * 4);
        float4 a1 = *reinterpret_cast<const float4*>(xr + 64 + tx * 4);
        unsigned long long a2[4];
        a2[0] = pk2(a0.x, a0.y); a2[1] = pk2(a0.z, a0.w);
        a2[2] = pk2(a1.x, a1.y); a2[3] = pk2(a1.z, a1.w);
        const float* wr = sw1 + k * H1 + ty * 8;
        float4 b0 = *reinterpret_cast<const float4*>(wr);
        float4 b1 = *reinterpret_cast<const float4*>(wr + 4);
        float bv[8] = {b0.x, b0.y, b0.z, b0.w, b1.x, b1.y, b1.z, b1.w};
#pragma unroll
        for (int jj = 0; jj < 8; jj++) {
            unsigned long long bd = pk2(bv[jj], bv[jj]);
            fma2(c2[jj][0], a2[0], bd);
            fma2(c2[jj][1], a2[1], bd);
            fma2(c2[jj][2], a2[2], bd);
            fma2(c2[jj][3], a2[3], bd);
        }
    }
    __syncthreads();   // Xs reads done; safe to overwrite with H1s

    // relu + store H1s[j][e]
#pragma unroll
    for (int jj = 0; jj < 8; jj++) {
        float r[8];
#pragma unroll
        for (int p = 0; p < 4; p++) {
            float lo, hi;
            upk2(c2[jj][p], lo, hi);
            r[2 * p]     = fmaxf(lo, 0.f);
            r[2 * p + 1] = fmaxf(hi, 0.f);
        }
        float* hp = sh1 + (ty * 8 + jj) * HSS1;
        *reinterpret_cast<float4*>(hp + tx * 4)      = make_float4(r[0], r[1], r[2], r[3]);
        *reinterpret_cast<float4*>(hp + 64 + tx * 4) = make_float4(r[4], r[5], r[6], r[7]);
    }
    __syncthreads();

    // ---------- GEMM2: XH[128e x 32c] ----------
    const int u2 = tid & 7;
    const int v2 = tid >> 3;

    unsigned long long d2[4][2];
    {
        unsigned long long s0 = pk2(sb2[u2 * 4],     sb2[u2 * 4 + 1]);
        unsigned long long s1 = pk2(sb2[u2 * 4 + 2], sb2[u2 * 4 + 3]);
#pragma unroll
        for (int ee = 0; ee < 4; ee++) { d2[ee][0] = s0; d2[ee][1] = s1; }
    }

#pragma unroll 4
    for (int k2 = 0; k2 < H1; k2++) {
        float4 av = *reinterpret_cast<const float4*>(sh1 + k2 * HSS1 + v2 * 4);
        float4 bw = *reinterpret_cast<const float4*>(sw2 + k2 * H2 + u2 * 4);
        unsigned long long bb0 = pk2(bw.x, bw.y);
        unsigned long long bb1 = pk2(bw.z, bw.w);
        float aa[4] = {av.x, av.y, av.z, av.w};
#pragma unroll
        for (int ee = 0; ee < 4; ee++) {
            unsigned long long ad = pk2(aa[ee], aa[ee]);
            fma2(d2[ee][0], ad, bb0);
            fma2(d2[ee][1], ad, bb1);
        }
    }

    // relu + dec-partial + width-8 shfl reduce -> g_part
#pragma unroll
    for (int ee = 0; ee < 4; ee++) {
        int ge = eblk + v2 * 4 + ee;
        float lo0, hi0, lo1, hi1;
        upk2(d2[ee][0], lo0, hi0);
        upk2(d2[ee][1], lo1, hi1);
        float r0 = fmaxf(lo0, 0.f), r1 = fmaxf(hi0, 0.f);
        float r2 = fmaxf(lo1, 0.f), r3 = fmaxf(hi1, 0.f);
        int c0 = u2 * 4;
        float p0 = r0 * sdw2[c0 * 2]       + r1 * sdw2[(c0 + 1) * 2]
                 + r2 * sdw2[(c0 + 2) * 2] + r3 * sdw2[(c0 + 3) * 2];
        float p1 = r0 * sdw2[c0 * 2 + 1]       + r1 * sdw2[(c0 + 1) * 2 + 1]
                 + r2 * sdw2[(c0 + 2) * 2 + 1] + r3 * sdw2[(c0 + 3) * 2 + 1];
#pragma unroll
        for (int off = 4; off > 0; off >>= 1) {
            p0 += __shfl_down_sync(0xffffffffu, p0, off, 8);
            p1 += __shfl_down_sync(0xffffffffu, p1, off, 8);
        }
        if (u2 == 0 && ge < n) g_part[ge] = make_float2(p0, p1);
    }
}

// ================= kernel 2: encoder + attention + decoder =================
#define TPB2 256
#define EPE 128   // elements per block (2 threads each: one per head)

// smem layout (floats)
#define E2_HSM  0                      // hv: [128][33] = 4224
#define E2_SENW (E2_HSM + EPE * 33)    // 256  (norm-folded enc weights)
#define E2_ENB  (E2_SENW + G * F * E)  // 32   (norm-folded enc bias)
#define E2_M    (E2_ENB + G * E)       // 32
#define E2_U    (E2_M + NH * 16)       // 8
#define E2_V    (E2_U + NH * 4)        // 8
#define E2_C    (E2_V + NH * 4)        // 2
#define E2_DH   (E2_C + NH)            // 64 = decw[64..127]  (hv rows)
#define E2_DA   (E2_DH + 64)           // 64 = decw[128..191] (att rows)
#define E2_DB   (E2_DA + 64)           // 2
#define E2_P2   (E2_DB + 2)            // 256 (head-1 partials)
#define E2_FLOATS (E2_P2 + EPE * 2)

extern "C" __global__ void __launch_bounds__(TPB2)
epi_kernel(const float* __restrict__ x,
           const float* __restrict__ norm_mean,
           const float* __restrict__ norm_std,
           const float* __restrict__ encw, const float* __restrict__ encb,
           const float* __restrict__ srcw, const float* __restrict__ srcb,
           const float* __restrict__ dstw, const float* __restrict__ dstb,
           const float* __restrict__ decw, const float* __restrict__ decb,
           float* __restrict__ out, int n)
{
    __shared__ float sm[E2_FLOATS];
    float* hsm  = sm + E2_HSM;
    float* senw = sm + E2_SENW;
    float* senb = sm + E2_ENB;
    float* sM   = sm + E2_M;
    float* su   = sm + E2_U;
    float* sv   = sm + E2_V;
    float* sc   = sm + E2_C;
    float* sdh  = sm + E2_DH;
    float* sda  = sm + E2_DA;
    float* sdb  = sm + E2_DB;
    float* sp2  = sm + E2_P2;

    const int tid = threadIdx.x;
    const int eblk = blockIdx.x * EPE;

    // ---- tables (norm folded into encoder weights/bias) ----
    if (tid < G * F * E) {
        int k = ((tid >> 5) << 3) + ((tid >> 2) & 7);   // g*8 + f
        senw[tid] = encw[tid] * (1.0f / (norm_std[k] + 1e-8f));
    }
    if (tid < G * E) {
        int g = tid >> 2, e4 = tid & 3;
        float acc = encb[tid];
        for (int f = 0; f < F; f++) {
            int k = g * 8 + f;
            acc -= norm_mean[k] * (1.0f / (norm_std[k] + 1e-8f)) * encw[g * 32 + f * 4 + e4];
        }
        senb[tid] = acc;
    }
    if (tid < 128) sdh[tid] = decw[64 + tid];   // covers DH(64) + DA(64), contiguous
    if (tid < OUTD) sdb[tid] = decb[tid];

    if (tid < NH) {
        const int hh = tid;
        const float invs = rsqrtf((float)AH);
        for (int e = 0; e < E; e++)
            for (int e2 = 0; e2 < E; e2++) {
                float m = 0.f;
                for (int a = 0; a < AH; a++)
                    m = fmaf(srcw[e * (NH * AH) + hh * AH + a],
                             dstw[e2 * (NH * AH) + hh * AH + a], m);
                sM[hh * 16 + e * 4 + e2] = m * invs;
            }
        for (int e = 0; e < E; e++) {
            float uu = 0.f, vv = 0.f;
            for (int a = 0; a < AH; a++) {
                uu = fmaf(srcw[e * (NH * AH) + hh * AH + a], dstb[hh * AH + a], uu);
                vv = fmaf(dstw[e * (NH * AH) + hh * AH + a], srcb[hh * AH + a], vv);
            }
            su[hh * 4 + e] = uu * invs;
            sv[hh * 4 + e] = vv * invs;
        }
        float cc = 0.f;
        for (int a = 0; a < AH; a++)
            cc = fmaf(srcb[hh * AH + a], dstb[hh * AH + a], cc);
        sc[hh] = cc * invs;
    }
    __syncthreads();

    // ---- phase A: threads 0..127 compute hv for their element ----
    if (tid < EPE) {
        int ge = eblk + tid;
        if (ge < n) {
            const float4* xr = reinterpret_cast<const float4*>(x + (size_t)ge * BD);
            float4 xq[16];
#pragma unroll
            for (int i = 0; i < 16; i++) xq[i] = __ldg(xr + i);
            const float* xs = reinterpret_cast<const float*>(xq);
#pragma unroll
            for (int g = 0; g < G; g++) {
#pragma unroll
                for (int e4 = 0; e4 < E; e4++) {
                    float acc = senb[g * E + e4];
#pragma unroll
                    for (int f = 0; f < F; f++)
                        acc = fmaf(xs[g * 8 + f], senw[g * 32 + f * 4 + e4], acc);
                    hsm[tid * 33 + g * E + e4] = fmaxf(acc, 0.f);
                }
            }
        }
    }
    __syncthreads();

    // ---- phase B: (element, head) per thread ----
    const int e = tid & (EPE - 1);
    const int h = tid >> 7;
    const int ge = eblk + e;
    float p0 = 0.f, p1 = 0.f;

    if (ge < n) {
        float hv[G * E];
#pragma unroll
        for (int i = 0; i < G * E; i++) hv[i] = hsm[e * 33 + i];

        float t[G * E];
        float sg[G], dk[G];
#pragma unroll
        for (int g = 0; g < G; g++) {
#pragma unroll
            for (int e2 = 0; e2 < E; e2++) {
                float acc = 0.f;
#pragma unroll
                for (int ee = 0; ee < E; ee++)
                    acc = fmaf(hv[g * E + ee], sM[h * 16 + ee * 4 + e2], acc);
                t[g * E + e2] = acc;
            }
            float a1 = 0.f, a2_ = 0.f;
#pragma unroll
            for (int ee = 0; ee < E; ee++) {
                a1  = fmaf(hv[g * E + ee], su[h * 4 + ee], a1);
                a2_ = fmaf(hv[g * E + ee], sv[h * 4 + ee], a2_);
            }
            sg[g] = a1;
            dk[g] = a2_;
        }
        const float cc = sc[h];

        float att[G * E];
#pragma unroll
        for (int i = 0; i < G * E; i++) att[i] = 0.f;

#pragma unroll
        for (int g = 0; g < G; g++) {
            float s[G];
            float mx = -1e30f;
#pragma unroll
            for (int k = 0; k < G; k++) {
                float acc = sg[g] + dk[k] + cc;
#pragma unroll
                for (int e2 = 0; e2 < E; e2++)
                    acc = fmaf(t[g * E + e2], hv[k * E + e2], acc);
                s[k] = acc;
                mx = fmaxf(mx, acc);
            }
            float p[G];
            float sum = 0.f;
#pragma unroll
            for (int k = 0; k < G; k++) {
                p[k] = __expf(s[k] - mx);
                sum += p[k];
            }
            float inv = 1.0f / sum;
#pragma unroll
            for (int k = 0; k < G; k++) {
                float pk = p[k] * inv;
#pragma unroll
                for (int ee = 0; ee < E; ee++)
                    att[g * E + ee] = fmaf(pk, hv[k * E + ee], att[g * E + ee]);
            }
        }

        // decoder partial: att rows (this head's contribution)
#pragma unroll
        for (int i = 0; i < G * E; i++) {
            p0 = fmaf(att[i], sda[i * 2 + 0], p0);
            p1 = fmaf(att[i], sda[i * 2 + 1], p1);
        }
        if (h == 0) {
            // hv rows + bias + mlp partial (xh rows)
#pragma unroll
            for (int i = 0; i < G * E; i++) {
                p0 = fmaf(hv[i], sdh[i * 2 + 0], p0);
                p1 = fmaf(hv[i], sdh[i * 2 + 1], p1);
            }
            float2 gp = g_part[ge];
            p0 += sdb[0] + gp.x;
            p1 += sdb[1] + gp.y;
        }
    }

    if (h == 1) {
        sp2[e * 2 + 0] = p0;
        sp2[e * 2 + 1] = p1;
    }
    __syncthreads();

    if (h == 0 && ge < n) {
        float2 r;
        r.x = p0 + sp2[e * 2 + 0];
        r.y = p1 + sp2[e * 2 + 1];
        reinterpret_cast<float2*>(out)[ge] = r;
    }
}

extern "C" void kernel_launch(void* const* d_in, const int* in_sizes, int n_in,
                              void* d_out, int out_size)
{
    const float* x     = (const float*)d_in[0];
    const float* mean_ = (const float*)d_in[1];
    const float* std_  = (const float*)d_in[2];
    const float* w1    = (const float*)d_in[3];
    const float* b1    = (const float*)d_in[4];
    const float* w2    = (const float*)d_in[5];
    const float* b2    = (const float*)d_in[6];
    const float* encw  = (const float*)d_in[7];
    const float* encb  = (const float*)d_in[8];
    const float* srcw  = (const float*)d_in[9];
    const float* srcb  = (const float*)d_in[10];
    const float* dstw  = (const float*)d_in[11];
    const float* dstb  = (const float*)d_in[12];
    const float* decw  = (const float*)d_in[13];
    const float* decb  = (const float*)d_in[14];
    float* out = (float*)d_out;

    int n = in_sizes[0] / BD;

    cudaFuncSetAttribute(mlp_kernel,
                         cudaFuncAttributeMaxDynamicSharedMemorySize, K1_BYTES);

    dim3 g1((n + EPB1 - 1) / EPB1);
    mlp_kernel<<<g1, TPB1, K1_BYTES>>>(x, w1, b1, w2, b2, decw, n);

    dim3 g2((n + EPE - 1) / EPE);
    epi_kernel<<<g2, TPB2>>>(x, mean_, std_, encw, encb,
                             srcw, srcb, dstw, dstb, decw, decb, out, n);
}